// round 1
// baseline (speedup 1.0000x reference)
#include <cuda_runtime.h>

// Problem constants
#define S_LEN 512
#define BS 64
#define IN 512
#define HD 512
#define G4 2048           // 4*H
#define MROWS (S_LEN*BS)  // 32768
#define NCTA_D 64         // CTAs per direction in recurrence

// ---------------- scratch (static device globals; no allocation) -------------
__device__ float g_xg[134217728];   // [2][512][64][2048] = 512MB
__device__ float g_h[2*BS*HD];      // current h per direction
__device__ unsigned g_bar[2];       // per-direction grid barrier counters

typedef unsigned long long ull;

__device__ __forceinline__ ull fma2(ull a, ull b, ull c){
    ull d; asm("fma.rn.f32x2 %0, %1, %2, %3;" : "=l"(d) : "l"(a), "l"(b), "l"(c));
    return d;
}
__device__ __forceinline__ ull pk(float x, float y){
    ull r; asm("mov.b64 %0, {%1, %2};" : "=l"(r)
               : "r"(__float_as_uint(x)), "r"(__float_as_uint(y)));
    return r;
}
__device__ __forceinline__ void upk(ull v, float& x, float& y){
    unsigned a, b; asm("mov.b64 {%0, %1}, %2;" : "=r"(a), "=r"(b) : "l"(v));
    x = __uint_as_float(a); y = __uint_as_float(b);
}

// ---------------- init: zero barriers, load initial h ------------------------
__global__ void init_k(const float* __restrict__ ih){
    int i = blockIdx.x * 256 + threadIdx.x;
    if (i < 2) g_bar[i] = 0u;
    if (i < 2*BS*HD) g_h[i] = ih[i];
}

// ---------------- phase 1: Xg = X @ W^T + (Wb + Rb) --------------------------
// A = X (32768 x 512) row-major; B = W[d] (2048 x 512) row-major; C (32768 x 2048)
__global__ void __launch_bounds__(256, 2) gemm_k(
    const float* __restrict__ X, const float* __restrict__ W,
    const float* __restrict__ Bv)
{
    __shared__ float As[16][128];
    __shared__ float Bs[16][128];
    const int d  = blockIdx.z;
    const int n0 = blockIdx.x * 128;
    const int m0 = blockIdx.y * 128;
    const int tid = threadIdx.x;
    const int tm = tid >> 4, tn = tid & 15;
    const float* Bm = W + (size_t)d * G4 * IN;

    ull acc[8][4];
    #pragma unroll
    for (int i = 0; i < 8; i++)
        #pragma unroll
        for (int j = 0; j < 4; j++) acc[i][j] = 0ull;

    const int lrow = tid >> 2;  // 0..63
    const int lkq  = tid & 3;

    for (int kt = 0; kt < IN; kt += 16){
        #pragma unroll
        for (int i = 0; i < 2; i++){
            int row = lrow + i*64;
            float4 va = *(const float4*)(X  + (size_t)(m0+row)*IN + kt + lkq*4);
            float4 vb = *(const float4*)(Bm + (size_t)(n0+row)*IN + kt + lkq*4);
            As[lkq*4+0][row]=va.x; As[lkq*4+1][row]=va.y;
            As[lkq*4+2][row]=va.z; As[lkq*4+3][row]=va.w;
            Bs[lkq*4+0][row]=vb.x; Bs[lkq*4+1][row]=vb.y;
            Bs[lkq*4+2][row]=vb.z; Bs[lkq*4+3][row]=vb.w;
        }
        __syncthreads();
        #pragma unroll
        for (int k = 0; k < 16; k++){
            float4 a0 = *(const float4*)&As[k][tm*8];
            float4 a1 = *(const float4*)&As[k][tm*8+4];
            ulonglong2 bb0 = *(const ulonglong2*)&Bs[k][tn*8];
            ulonglong2 bb1 = *(const ulonglong2*)&Bs[k][tn*8+4];
            float av[8] = {a0.x,a0.y,a0.z,a0.w,a1.x,a1.y,a1.z,a1.w};
            ull   bv[4] = {bb0.x, bb0.y, bb1.x, bb1.y};
            #pragma unroll
            for (int i = 0; i < 8; i++){
                ull aa = pk(av[i], av[i]);
                #pragma unroll
                for (int j = 0; j < 4; j++) acc[i][j] = fma2(aa, bv[j], acc[i][j]);
            }
        }
        __syncthreads();
    }

    float bias[8];
    #pragma unroll
    for (int j = 0; j < 8; j++){
        int n = n0 + tn*8 + j;
        bias[j] = Bv[(size_t)d*4096 + n] + Bv[(size_t)d*4096 + 2048 + n];
    }
    float* op = g_xg + (size_t)d * MROWS * G4;
    #pragma unroll
    for (int i = 0; i < 8; i++){
        int m = m0 + tm*8 + i;
        float r[8];
        #pragma unroll
        for (int j = 0; j < 4; j++) upk(acc[i][j], r[2*j], r[2*j+1]);
        #pragma unroll
        for (int j = 0; j < 8; j++) r[j] += bias[j];
        float4* o4 = (float4*)(op + (size_t)m * G4 + n0 + tn*8);
        o4[0] = make_float4(r[0], r[1], r[2], r[3]);
        o4[1] = make_float4(r[4], r[5], r[6], r[7]);
    }
}

// ---------------- phase 2: persistent recurrence -----------------------------
// grid = 128 CTAs: blockIdx/64 = direction, blockIdx%64 = column-block (8 h cols).
// R slice (32 rows x 512) lives in registers for the whole kernel.
// SMEM layout (dynamic):
#define SM_H    0
#define SM_XG   131072
#define SM_GT   139264
#define SM_C    147456
#define SM_H0   149504
#define SM_C0   151552
#define SM_LEN  153600
#define SM_P    153856
#define REC_SMEM 153984

__global__ void __launch_bounds__(256, 1) rec_k(
    const float* __restrict__ Rw, const float* __restrict__ P,
    const int*  __restrict__ lens, const float* __restrict__ ih,
    const float* __restrict__ ic,  float* __restrict__ out)
{
    extern __shared__ char sm[];
    float* h_s  = (float*)(sm + SM_H);    // [64][512]
    float* xg_s = (float*)(sm + SM_XG);   // [64][32]
    float* gt_s = (float*)(sm + SM_GT);   // [64][32]
    float* c_s  = (float*)(sm + SM_C);    // [64][8]
    float* h0_s = (float*)(sm + SM_H0);
    float* c0_s = (float*)(sm + SM_C0);
    int*   len_s= (int*)  (sm + SM_LEN);
    float* P_s  = (float*)(sm + SM_P);    // [3][8]: i, f, o

    const int tid = threadIdx.x;
    const int d  = blockIdx.x >> 6;
    const int cb = blockIdx.x & 63;
    const int jb = cb * 8;
    const int w  = tid >> 5, l = tid & 31;

    // R (32 rows x 512 k) into registers: warp w owns local rows w*4..w*4+3,
    // lane l owns k in {c*128 + l*4 + 0..3 : c=0..3}
    ull rA[4][4], rB[4][4];
    {
        const float* Rd = Rw + (size_t)d * G4 * HD;
        #pragma unroll
        for (int rr = 0; rr < 4; rr++){
            int lr = w*4 + rr; int q = lr >> 3; int jj = lr & 7;
            const float* rrow = Rd + (size_t)(q*HD + jb + jj) * HD;
            #pragma unroll
            for (int c = 0; c < 4; c++){
                ulonglong2 v = *(const ulonglong2*)(rrow + c*128 + l*4);
                rA[rr][c] = v.x; rB[rr][c] = v.y;
            }
        }
    }
    if (tid < 64) len_s[tid] = lens[tid];
    if (tid < 24){
        int q = tid >> 3, jj = tid & 7;  // q: 0=i,1=f,2=o (P layout)
        P_s[tid] = P[(size_t)d*3*HD + q*HD + jb + jj];
    }
    for (int p = tid; p < 512; p += 256){
        int b = p >> 3, jj = p & 7;
        float hv = ih[(size_t)d*BS*HD + b*HD + jb + jj];
        float cv = ic[(size_t)d*BS*HD + b*HD + jb + jj];
        h0_s[p] = hv; c0_s[p] = cv; c_s[p] = cv;
    }
    __syncthreads();

    const float4* hb4 = (const float4*)(g_h + d*BS*HD);
    float4* hs4 = (float4*)h_s;
    volatile unsigned* vb = g_bar;

    for (int s_ = 0; s_ < S_LEN; s_++){
        const int t = d ? (S_LEN-1-s_) : s_;

        // stage h (L2, bypass stale L1) and this step's xg slice
        #pragma unroll 8
        for (int i = tid; i < BS*HD/4; i += 256) hs4[i] = __ldcg(hb4 + i);
        {
            const float4* xb = (const float4*)(g_xg + (((size_t)d*S_LEN + t)*BS)*G4);
            float4* xs4 = (float4*)xg_s;
            #pragma unroll
            for (int it = 0; it < 2; it++){
                int f = tid + it*256;                // 0..511
                int b = f >> 3, rem = f & 7, q = rem >> 1, hh = rem & 1;
                xs4[f] = xb[(size_t)b*(G4/4) + q*(HD/4) + (jb>>2) + hh];
            }
        }
        __syncthreads();

        // GEMV: warp w -> local rows w*4..w*4+3, all 64 batches
        const ulonglong2* h2 = (const ulonglong2*)h_s;
        #pragma unroll 2
        for (int b = 0; b < BS; b++){
            ull a0=0ull, a1=0ull, a2=0ull, a3=0ull;
            #pragma unroll
            for (int c = 0; c < 4; c++){
                ulonglong2 hv = h2[b*128 + c*32 + l];
                a0 = fma2(hv.x, rA[0][c], a0); a0 = fma2(hv.y, rB[0][c], a0);
                a1 = fma2(hv.x, rA[1][c], a1); a1 = fma2(hv.y, rB[1][c], a1);
                a2 = fma2(hv.x, rA[2][c], a2); a2 = fma2(hv.y, rB[2][c], a2);
                a3 = fma2(hv.x, rA[3][c], a3); a3 = fma2(hv.y, rB[3][c], a3);
            }
            float s0,s1,s2,s3,x,y;
            upk(a0,x,y); s0 = x+y;  upk(a1,x,y); s1 = x+y;
            upk(a2,x,y); s2 = x+y;  upk(a3,x,y); s3 = x+y;
            #pragma unroll
            for (int off = 16; off; off >>= 1){
                s0 += __shfl_down_sync(0xffffffffu, s0, off);
                s1 += __shfl_down_sync(0xffffffffu, s1, off);
                s2 += __shfl_down_sync(0xffffffffu, s2, off);
                s3 += __shfl_down_sync(0xffffffffu, s3, off);
            }
            if (l == 0) *(float4*)(gt_s + b*32 + w*4) = make_float4(s0,s1,s2,s3);
        }
        __syncthreads();

        // elementwise gates (ONNX row order: q0=i, q1=o, q2=f, q3=c~)
        #pragma unroll
        for (int it = 0; it < 2; it++){
            int p = tid + it*256;
            int b = p >> 3, jj = p & 7;
            float gi = gt_s[b*32      + jj] + xg_s[b*32      + jj];
            float go = gt_s[b*32 +  8 + jj] + xg_s[b*32 +  8 + jj];
            float gf = gt_s[b*32 + 16 + jj] + xg_s[b*32 + 16 + jj];
            float gc = gt_s[b*32 + 24 + jj] + xg_s[b*32 + 24 + jj];
            float co = c_s[p];
            float i_t = 1.f/(1.f + __expf(-(gi + P_s[     jj]*co)));
            float f_t = 1.f/(1.f + __expf(-(gf + P_s[ 8 + jj]*co)));
            float ct  = tanhf(gc);
            float cn  = f_t*co + i_t*ct;
            float o_t = 1.f/(1.f + __expf(-(go + P_s[16 + jj]*cn)));
            float hn  = o_t * tanhf(cn);
            if (t >= len_s[b]){ hn = h0_s[p]; cn = c0_s[p]; }
            c_s[p] = cn;
            g_h[d*BS*HD + b*HD + jb + jj] = hn;
            out[(((size_t)t*2 + d)*BS + b)*HD + jb + jj] = hn;
        }
        __threadfence();
        __syncthreads();
        if (tid == 0){
            atomicAdd(&g_bar[d], 1u);
            unsigned target = (unsigned)(NCTA_D * (s_ + 1));
            while (vb[d] < target) { }
            __threadfence();
        }
        __syncthreads();
    }

    // final Y_h, Y_c
    const size_t SY = (size_t)S_LEN * 2 * BS * HD;
    #pragma unroll
    for (int it = 0; it < 2; it++){
        int p = tid + it*256;
        int b = p >> 3, jj = p & 7;
        float hf = g_h[d*BS*HD + b*HD + jb + jj];
        out[SY +             ((size_t)d*BS + b)*HD + jb + jj] = hf;
        out[SY + 2*BS*HD +   ((size_t)d*BS + b)*HD + jb + jj] = c_s[p];
    }
}

// ---------------- launch -----------------------------------------------------
extern "C" void kernel_launch(void* const* d_in, const int* in_sizes, int n_in,
                              void* d_out, int out_size)
{
    const float* X    = (const float*)d_in[0];
    const float* W    = (const float*)d_in[1];
    const float* R    = (const float*)d_in[2];
    const float* B    = (const float*)d_in[3];
    const int*   lens = (const int*  )d_in[4];
    const float* ih   = (const float*)d_in[5];
    const float* ic   = (const float*)d_in[6];
    const float* P    = (const float*)d_in[7];
    float* out = (float*)d_out;

    cudaFuncSetAttribute(rec_k, cudaFuncAttributeMaxDynamicSharedMemorySize, REC_SMEM);

    init_k<<<256, 256>>>(ih);
    dim3 gg(G4/128, MROWS/128, 2);
    gemm_k<<<gg, 256>>>(X, W, B);
    rec_k<<<128, 256, REC_SMEM>>>(R, P, lens, ih, ic, out);
}

// round 3
// speedup vs baseline: 1.1938x; 1.1938x over previous
#include <cuda_runtime.h>
#include <cuda_bf16.h>
#include <cstdint>

// Problem constants
#define S_LEN 512
#define BS 64
#define IN 512
#define HD 512
#define G4 2048           // 4*H
#define MROWS (S_LEN*BS)  // 32768
#define NCTA_D 64         // CTAs per direction in recurrence

// ---------------- scratch (static device globals; no allocation) -------------
__device__ __align__(16) float g_xg[134217728];        // [2][512][64][2048] = 512MB
__device__ __align__(16) float g_h[2*BS*HD];           // current h per direction
__device__ unsigned g_bar[2];                          // per-direction barriers
__device__ __align__(16) __nv_bfloat16 g_xh[MROWS*IN]; // X hi (bf16)
__device__ __align__(16) __nv_bfloat16 g_xl[MROWS*IN]; // X lo
__device__ __align__(16) __nv_bfloat16 g_wh[2*G4*IN];  // W hi
__device__ __align__(16) __nv_bfloat16 g_wl[2*G4*IN];  // W lo

typedef unsigned long long ull;

__device__ __forceinline__ ull fma2(ull a, ull b, ull c){
    ull d; asm("fma.rn.f32x2 %0, %1, %2, %3;" : "=l"(d) : "l"(a), "l"(b), "l"(c));
    return d;
}
__device__ __forceinline__ void upk(ull v, float& x, float& y){
    unsigned a, b; asm("mov.b64 {%0, %1}, %2;" : "=r"(a), "=r"(b) : "l"(v));
    x = __uint_as_float(a); y = __uint_as_float(b);
}

// ---------------- sm_80-class primitives (compute_103-safe) ------------------
__device__ __forceinline__ uint32_t s2u(const void* p){
    uint32_t a;
    asm("{ .reg .u64 t; cvta.to.shared.u64 t, %1; cvt.u32.u64 %0, t; }" : "=r"(a) : "l"(p));
    return a;
}
__device__ __forceinline__ void cp16(uint32_t s, const void* g){
    asm volatile("cp.async.cg.shared.global [%0], [%1], 16;" :: "r"(s), "l"(g) : "memory");
}
__device__ __forceinline__ void cp_commit(){
    asm volatile("cp.async.commit_group;" ::: "memory");
}
__device__ __forceinline__ void ldsm4(uint32_t& r0, uint32_t& r1, uint32_t& r2, uint32_t& r3,
                                      uint32_t addr){
    asm volatile("ldmatrix.sync.aligned.m8n8.x4.shared.b16 {%0,%1,%2,%3}, [%4];"
                 : "=r"(r0), "=r"(r1), "=r"(r2), "=r"(r3) : "r"(addr));
}
__device__ __forceinline__ void mma_bf16(float* c, const uint32_t* a, uint32_t b0, uint32_t b1){
    asm volatile(
      "mma.sync.aligned.m16n8k16.row.col.f32.bf16.bf16.f32 "
      "{%0,%1,%2,%3}, {%4,%5,%6,%7}, {%8,%9}, {%0,%1,%2,%3};"
      : "+f"(c[0]), "+f"(c[1]), "+f"(c[2]), "+f"(c[3])
      : "r"(a[0]), "r"(a[1]), "r"(a[2]), "r"(a[3]), "r"(b0), "r"(b1));
}
__device__ __forceinline__ uint32_t swz(uint32_t o){ return o ^ ((o >> 3) & 0x70); }

// ---------------- init: zero barriers, load initial h ------------------------
__global__ void init_k(const float* __restrict__ ih){
    int i = blockIdx.x * 256 + threadIdx.x;
    if (i < 2) g_bar[i] = 0u;
    if (i < 2*BS*HD) g_h[i] = ih[i];
}

// ---------------- phase 0: fp32 -> bf16 hi/lo split --------------------------
__global__ void conv_k(const float* __restrict__ X, const float* __restrict__ W){
    int i = blockIdx.x * 256 + threadIdx.x;
    const int NX = MROWS * IN;
    const int NW = 2 * G4 * IN;
    if (i < NX){
        float x = X[i];
        __nv_bfloat16 h = __float2bfloat16(x);
        g_xh[i] = h;
        g_xl[i] = __float2bfloat16(x - __bfloat162float(h));
    } else if (i < NX + NW){
        int j = i - NX;
        float x = W[j];
        __nv_bfloat16 h = __float2bfloat16(x);
        g_wh[j] = h;
        g_wl[j] = __float2bfloat16(x - __bfloat162float(h));
    }
}

// ---------------- phase 1: Xg = X @ W^T + (Wb+Rb), HMMA bf16 split -----------
// CTA tile 128(M) x 128(N); K in 8 chunks of 64; 3 passes (hh, hl, lh).
// SMEM: [64..576) bias | [1024..) 2 stages x 64KB {Ah, Al, Bh, Bl} x 16KB.
#define GSM_BUF 1024
#define GSM_TOT (1024 + 2*65536)

__device__ __forceinline__ void g_issue(
    uint32_t tb, int tid, int c,
    const __nv_bfloat16* sA0, const __nv_bfloat16* sA1,
    const __nv_bfloat16* sB0, const __nv_bfloat16* sB1)
{
    const __nv_bfloat16* srcs[4] = {sA0, sA1, sB0, sB1};
    #pragma unroll
    for (int a = 0; a < 4; a++){
        const __nv_bfloat16* g = srcs[a] + c * 64;
        #pragma unroll
        for (int it = 0; it < 4; it++){
            int s = tid + it * 256;          // 0..1023
            int row = s >> 3, seg = s & 7;
            cp16(tb + a*16384 + swz((uint32_t)(row*128 + seg*16)),
                 g + (size_t)row * IN + seg*8);
        }
    }
    cp_commit();
}

__global__ void __launch_bounds__(256, 1) tcgemm_k(const float* __restrict__ Bv)
{
    extern __shared__ char sm[];
    const uint32_t sb = s2u(sm);
    const int tid = threadIdx.x;
    const int w = tid >> 5, l = tid & 31;
    const int wm = w >> 2, wn = w & 3;       // warp tile: 64(M) x 32(N)
    const int n0 = blockIdx.x * 128, m0 = blockIdx.y * 128, d = blockIdx.z;

    if (tid < 128)
        ((float*)(sm + 64))[tid] = Bv[d*4096 + n0 + tid] + Bv[d*4096 + 2048 + n0 + tid];

    const __nv_bfloat16* sA0 = g_xh + (size_t)m0 * IN;
    const __nv_bfloat16* sA1 = g_xl + (size_t)m0 * IN;
    const __nv_bfloat16* sB0 = g_wh + ((size_t)d * G4 + n0) * IN;
    const __nv_bfloat16* sB1 = g_wl + ((size_t)d * G4 + n0) * IN;

    float acc[4][4][4];
    #pragma unroll
    for (int i = 0; i < 4; i++)
        #pragma unroll
        for (int j = 0; j < 4; j++)
            #pragma unroll
            for (int q = 0; q < 4; q++) acc[i][j][q] = 0.f;

    g_issue(sb + GSM_BUF, tid, 0, sA0, sA1, sB0, sB1);

    // ldmatrix lane addressing (fixed per thread)
    const uint32_t a_off = (uint32_t)((wm*64 + (l & 15)) * 128 + (l >> 4) * 16);
    const uint32_t b_off = (uint32_t)((wn*32 + (l & 7) + ((l >> 4) & 1) * 8) * 128
                                      + ((l >> 3) & 1) * 16);

    #pragma unroll 1
    for (int c = 0; c < 8; c++){
        const uint32_t tb = sb + GSM_BUF + (c & 1) * 65536;
        if (c < 7) g_issue(sb + GSM_BUF + ((c+1) & 1) * 65536, tid, c+1, sA0, sA1, sB0, sB1);
        if (c < 7) asm volatile("cp.async.wait_group 1;" ::: "memory");
        else       asm volatile("cp.async.wait_group 0;" ::: "memory");
        __syncthreads();

        #pragma unroll
        for (int p = 0; p < 3; p++){
            const uint32_t aB = tb + (p == 2 ? 16384u : 0u);
            const uint32_t bB = tb + 32768u + (p == 1 ? 16384u : 0u);
            #pragma unroll
            for (int ks = 0; ks < 4; ks++){
                uint32_t af[4][4];
                #pragma unroll
                for (int mt = 0; mt < 4; mt++)
                    ldsm4(af[mt][0], af[mt][1], af[mt][2], af[mt][3],
                          aB + swz(a_off + (uint32_t)(ks*32 + mt*2048)));
                uint32_t bf[2][4];
                #pragma unroll
                for (int bt = 0; bt < 2; bt++)
                    ldsm4(bf[bt][0], bf[bt][1], bf[bt][2], bf[bt][3],
                          bB + swz(b_off + (uint32_t)(ks*32 + bt*2048)));
                #pragma unroll
                for (int mt = 0; mt < 4; mt++){
                    #pragma unroll
                    for (int nt = 0; nt < 4; nt++)
                        mma_bf16(acc[mt][nt], af[mt],
                                 bf[nt >> 1][(nt & 1)*2], bf[nt >> 1][(nt & 1)*2 + 1]);
                }
            }
        }
        __syncthreads();
    }

    // epilogue: add bias, write fp32
    const float* bias = (const float*)(sm + 64);
    float* op = g_xg + (size_t)d * MROWS * G4;
    #pragma unroll
    for (int mt = 0; mt < 4; mt++){
        int mrow = m0 + wm*64 + mt*16 + (l >> 2);
        #pragma unroll
        for (int nt = 0; nt < 4; nt++){
            int nc = wn*32 + nt*8 + 2*(l & 3);
            float b0 = bias[nc], b1 = bias[nc + 1];
            float2 v0 = make_float2(acc[mt][nt][0] + b0, acc[mt][nt][1] + b1);
            float2 v1 = make_float2(acc[mt][nt][2] + b0, acc[mt][nt][3] + b1);
            *(float2*)(op + (size_t)mrow * G4 + n0 + nc) = v0;
            *(float2*)(op + (size_t)(mrow + 8) * G4 + n0 + nc) = v1;
        }
    }
}

// ---------------- phase 2: persistent recurrence -----------------------------
#define SM_H    0
#define SM_XG   131072
#define SM_GT   139264
#define SM_C    147456
#define SM_H0   149504
#define SM_C0   151552
#define SM_LEN  153600
#define SM_P    153856
#define REC_SMEM 153984

__global__ void __launch_bounds__(256, 1) rec_k(
    const float* __restrict__ Rw, const float* __restrict__ P,
    const int*  __restrict__ lens, const float* __restrict__ ih,
    const float* __restrict__ ic,  float* __restrict__ out)
{
    extern __shared__ char sm[];
    float* h_s  = (float*)(sm + SM_H);    // [64][512]
    float* xg_s = (float*)(sm + SM_XG);   // [64][32]
    float* gt_s = (float*)(sm + SM_GT);   // [64][32]
    float* c_s  = (float*)(sm + SM_C);    // [64][8]
    float* h0_s = (float*)(sm + SM_H0);
    float* c0_s = (float*)(sm + SM_C0);
    int*   len_s= (int*)  (sm + SM_LEN);
    float* P_s  = (float*)(sm + SM_P);    // [3][8]: i, f, o

    const int tid = threadIdx.x;
    const int d  = blockIdx.x >> 6;
    const int cb = blockIdx.x & 63;
    const int jb = cb * 8;
    const int w  = tid >> 5, l = tid & 31;

    ull rA[4][4], rB[4][4];
    {
        const float* Rd = Rw + (size_t)d * G4 * HD;
        #pragma unroll
        for (int rr = 0; rr < 4; rr++){
            int lr = w*4 + rr; int q = lr >> 3; int jj = lr & 7;
            const float* rrow = Rd + (size_t)(q*HD + jb + jj) * HD;
            #pragma unroll
            for (int c = 0; c < 4; c++){
                ulonglong2 v = *(const ulonglong2*)(rrow + c*128 + l*4);
                rA[rr][c] = v.x; rB[rr][c] = v.y;
            }
        }
    }
    if (tid < 64) len_s[tid] = lens[tid];
    if (tid < 24){
        int q = tid >> 3, jj = tid & 7;
        P_s[tid] = P[(size_t)d*3*HD + q*HD + jb + jj];
    }
    for (int p = tid; p < 512; p += 256){
        int b = p >> 3, jj = p & 7;
        float hv = ih[(size_t)d*BS*HD + b*HD + jb + jj];
        float cv = ic[(size_t)d*BS*HD + b*HD + jb + jj];
        h0_s[p] = hv; c0_s[p] = cv; c_s[p] = cv;
    }
    __syncthreads();

    const float4* hb4 = (const float4*)(g_h + d*BS*HD);
    float4* hs4 = (float4*)h_s;
    volatile unsigned* vb = g_bar;

    for (int s_ = 0; s_ < S_LEN; s_++){
        const int t = d ? (S_LEN-1-s_) : s_;

        #pragma unroll 8
        for (int i = tid; i < BS*HD/4; i += 256) hs4[i] = __ldcg(hb4 + i);
        {
            const float4* xb = (const float4*)(g_xg + (((size_t)d*S_LEN + t)*BS)*G4);
            float4* xs4 = (float4*)xg_s;
            #pragma unroll
            for (int it = 0; it < 2; it++){
                int f = tid + it*256;
                int b = f >> 3, rem = f & 7, q = rem >> 1, hh = rem & 1;
                xs4[f] = xb[(size_t)b*(G4/4) + q*(HD/4) + (jb>>2) + hh];
            }
        }
        __syncthreads();

        const ulonglong2* h2 = (const ulonglong2*)h_s;
        #pragma unroll 2
        for (int b = 0; b < BS; b++){
            ull a0=0ull, a1=0ull, a2=0ull, a3=0ull;
            #pragma unroll
            for (int c = 0; c < 4; c++){
                ulonglong2 hv = h2[b*128 + c*32 + l];
                a0 = fma2(hv.x, rA[0][c], a0); a0 = fma2(hv.y, rB[0][c], a0);
                a1 = fma2(hv.x, rA[1][c], a1); a1 = fma2(hv.y, rB[1][c], a1);
                a2 = fma2(hv.x, rA[2][c], a2); a2 = fma2(hv.y, rB[2][c], a2);
                a3 = fma2(hv.x, rA[3][c], a3); a3 = fma2(hv.y, rB[3][c], a3);
            }
            float s0,s1,s2,s3,x,y;
            upk(a0,x,y); s0 = x+y;  upk(a1,x,y); s1 = x+y;
            upk(a2,x,y); s2 = x+y;  upk(a3,x,y); s3 = x+y;
            #pragma unroll
            for (int off = 16; off; off >>= 1){
                s0 += __shfl_down_sync(0xffffffffu, s0, off);
                s1 += __shfl_down_sync(0xffffffffu, s1, off);
                s2 += __shfl_down_sync(0xffffffffu, s2, off);
                s3 += __shfl_down_sync(0xffffffffu, s3, off);
            }
            if (l == 0) *(float4*)(gt_s + b*32 + w*4) = make_float4(s0,s1,s2,s3);
        }
        __syncthreads();

        #pragma unroll
        for (int it = 0; it < 2; it++){
            int p = tid + it*256;
            int b = p >> 3, jj = p & 7;
            float gi = gt_s[b*32      + jj] + xg_s[b*32      + jj];
            float go = gt_s[b*32 +  8 + jj] + xg_s[b*32 +  8 + jj];
            float gf = gt_s[b*32 + 16 + jj] + xg_s[b*32 + 16 + jj];
            float gc = gt_s[b*32 + 24 + jj] + xg_s[b*32 + 24 + jj];
            float co = c_s[p];
            float i_t = 1.f/(1.f + __expf(-(gi + P_s[     jj]*co)));
            float f_t = 1.f/(1.f + __expf(-(gf + P_s[ 8 + jj]*co)));
            float ct  = tanhf(gc);
            float cn  = f_t*co + i_t*ct;
            float o_t = 1.f/(1.f + __expf(-(go + P_s[16 + jj]*cn)));
            float hn  = o_t * tanhf(cn);
            if (t >= len_s[b]){ hn = h0_s[p]; cn = c0_s[p]; }
            c_s[p] = cn;
            g_h[d*BS*HD + b*HD + jb + jj] = hn;
            out[(((size_t)t*2 + d)*BS + b)*HD + jb + jj] = hn;
        }
        __threadfence();
        __syncthreads();
        if (tid == 0){
            atomicAdd(&g_bar[d], 1u);
            unsigned target = (unsigned)(NCTA_D * (s_ + 1));
            while (vb[d] < target) { }
            __threadfence();
        }
        __syncthreads();
    }

    const size_t SY = (size_t)S_LEN * 2 * BS * HD;
    #pragma unroll
    for (int it = 0; it < 2; it++){
        int p = tid + it*256;
        int b = p >> 3, jj = p & 7;
        float hf = g_h[d*BS*HD + b*HD + jb + jj];
        out[SY +             ((size_t)d*BS + b)*HD + jb + jj] = hf;
        out[SY + 2*BS*HD +   ((size_t)d*BS + b)*HD + jb + jj] = c_s[p];
    }
}

// ---------------- launch -----------------------------------------------------
extern "C" void kernel_launch(void* const* d_in, const int* in_sizes, int n_in,
                              void* d_out, int out_size)
{
    const float* X    = (const float*)d_in[0];
    const float* W    = (const float*)d_in[1];
    const float* R    = (const float*)d_in[2];
    const float* B    = (const float*)d_in[3];
    const int*   lens = (const int*  )d_in[4];
    const float* ih   = (const float*)d_in[5];
    const float* ic   = (const float*)d_in[6];
    const float* P    = (const float*)d_in[7];
    float* out = (float*)d_out;

    cudaFuncSetAttribute(rec_k, cudaFuncAttributeMaxDynamicSharedMemorySize, REC_SMEM);
    cudaFuncSetAttribute(tcgemm_k, cudaFuncAttributeMaxDynamicSharedMemorySize, GSM_TOT);

    init_k<<<256, 256>>>(ih);
    {
        int tot = MROWS*IN + 2*G4*IN;
        conv_k<<<(tot + 255)/256, 256>>>(X, W);
    }
    dim3 gg(G4/128, MROWS/128, 2);
    tcgemm_k<<<gg, 256, GSM_TOT>>>(B);
    rec_k<<<128, 256, REC_SMEM>>>(R, P, lens, ih, ic, out);
}